// round 7
// baseline (speedup 1.0000x reference)
#include <cuda_runtime.h>
#include <cuda_fp16.h>
#include <cstdint>

#define BTOT 4
#define NTOK 4096
#define CCH  128
#define TOKENS_ALL (BTOT * NTOK)
#define TILE 128
#define NT (NTOK / TILE)

// f16 scratch for projected q (pre-scaled by 1/sqrt(C)), k, v
__device__ __half g_q[TOKENS_ALL * CCH];
__device__ __half g_k[TOKENS_ALL * CCH];
__device__ __half g_v[TOKENS_ALL * CCH];

extern __shared__ char dyn_smem[];

// ---------------------------------------------------------------------------
// helpers
// ---------------------------------------------------------------------------
__device__ __forceinline__ uint32_t smem_u32(const void* p) {
    uint32_t a;
    asm("{ .reg .u64 t; cvta.to.shared.u64 t, %1; cvt.u32.u64 %0, t; }"
        : "=r"(a) : "l"(p));
    return a;
}
__device__ __forceinline__ void cp16(uint32_t dst, const void* src) {
    asm volatile("cp.async.cg.shared.global [%0], [%1], 16;"
                 :: "r"(dst), "l"(src) : "memory");
}
__device__ __forceinline__ void cp_commit() {
    asm volatile("cp.async.commit_group;" ::: "memory");
}
__device__ __forceinline__ void cp_wait_all() {
    asm volatile("cp.async.wait_group 0;" ::: "memory");
}
__device__ __forceinline__ void ldm4(uint32_t (&r)[4], uint32_t a) {
    asm volatile("ldmatrix.sync.aligned.m8n8.x4.shared.b16 {%0,%1,%2,%3}, [%4];"
                 : "=r"(r[0]), "=r"(r[1]), "=r"(r[2]), "=r"(r[3]) : "r"(a));
}
__device__ __forceinline__ void ldm4t(uint32_t (&r)[4], uint32_t a) {
    asm volatile("ldmatrix.sync.aligned.m8n8.x4.trans.shared.b16 {%0,%1,%2,%3}, [%4];"
                 : "=r"(r[0]), "=r"(r[1]), "=r"(r[2]), "=r"(r[3]) : "r"(a));
}
// f16 inputs, f32 accumulators
__device__ __forceinline__ void mma_f32(float (&d)[4], const uint32_t (&a)[4],
                                        uint32_t b0, uint32_t b1) {
    asm volatile(
        "mma.sync.aligned.m16n8k16.row.col.f32.f16.f16.f32 "
        "{%0,%1,%2,%3}, {%4,%5,%6,%7}, {%8,%9}, {%0,%1,%2,%3};"
        : "+f"(d[0]), "+f"(d[1]), "+f"(d[2]), "+f"(d[3])
        : "r"(a[0]), "r"(a[1]), "r"(a[2]), "r"(a[3]), "r"(b0), "r"(b1));
}
// f16 inputs, f16 accumulators (2 packed regs)
__device__ __forceinline__ void mma_f16(uint32_t (&d)[2], const uint32_t (&a)[4],
                                        uint32_t b0, uint32_t b1) {
    asm volatile(
        "mma.sync.aligned.m16n8k16.row.col.f16.f16.f16.f16 "
        "{%0,%1}, {%2,%3,%4,%5}, {%6,%7}, {%0,%1};"
        : "+r"(d[0]), "+r"(d[1])
        : "r"(a[0]), "r"(a[1]), "r"(a[2]), "r"(a[3]), "r"(b0), "r"(b1));
}
__device__ __forceinline__ uint32_t packh(float hi, float lo) {
    __half2 h = __floats2half2_rn(lo, hi);   // x = lo, y = hi
    return *reinterpret_cast<uint32_t*>(&h);
}
__device__ __forceinline__ void sts128(uint32_t a, uint32_t r0, uint32_t r1,
                                       uint32_t r2, uint32_t r3) {
    asm volatile("st.shared.v4.b32 [%0], {%1,%2,%3,%4};"
                 :: "r"(a), "r"(r0), "r"(r1), "r"(r2), "r"(r3) : "memory");
}
// 16B-chunk swizzle within a 256B row: conflict-free ldmatrix + cp.async
__device__ __forceinline__ int swz(int c, int r) {
    return (c & 8) | ((c ^ r) & 7);
}

// ---------------------------------------------------------------------------
// Kernel 1: fused QKV projection on mma.sync f16 (f32 accum).
// CTA = 128 tokens, 8 warps x 16 tokens. SMEM: x 32KB, Wq/Wk/Wv 32KB each.
// ---------------------------------------------------------------------------
#define QOFF_X 0u
#define QOFF_W 32768u
#define QKV_SMEM (32768 * 4)

__global__ __launch_bounds__(256, 1) void qkv_mma(
    const float* __restrict__ x,
    const float* __restrict__ Wq, const float* __restrict__ bq,
    const float* __restrict__ Wk, const float* __restrict__ bk,
    const float* __restrict__ Wv, const float* __restrict__ bv)
{
    uint32_t smb = smem_u32(dyn_smem);
    const int tid = threadIdx.x, wid = tid >> 5, lane = tid & 31;
    const int g = lane >> 2, tg = lane & 3;
    const int tok0 = blockIdx.x * 128;

    // ---- stage x (fp32 -> f16, swizzled 16B chunks) ----
    #pragma unroll
    for (int it = 0; it < 8; ++it) {
        int idx = it * 256 + tid;
        int row = idx >> 4, c = idx & 15;
        const float* src = x + (size_t)(tok0 + row) * CCH + 8 * c;
        float4 a = *(const float4*)src;
        float4 b2 = *(const float4*)(src + 4);
        uint32_t dst = smb + QOFF_X + (uint32_t)(row * 256 + swz(c, row) * 16);
        sts128(dst, packh(a.y, a.x), packh(a.w, a.z),
                    packh(b2.y, b2.x), packh(b2.w, b2.z));
    }
    const float* Wmat[3] = {Wq, Wk, Wv};
    #pragma unroll
    for (int m = 0; m < 3; ++m) {
        #pragma unroll
        for (int it = 0; it < 8; ++it) {
            int idx = it * 256 + tid;
            int row = idx >> 4, c = idx & 15;
            const float* src = Wmat[m] + (size_t)row * CCH + 8 * c;
            float4 a = *(const float4*)src;
            float4 b2 = *(const float4*)(src + 4);
            uint32_t dst = smb + QOFF_W + (uint32_t)m * 32768u +
                           (uint32_t)(row * 256 + swz(c, row) * 16);
            sts128(dst, packh(a.y, a.x), packh(a.w, a.z),
                        packh(b2.y, b2.x), packh(b2.w, b2.z));
        }
    }
    __syncthreads();

    uint32_t xa[8][4];
    {
        int xrow = 16 * wid + (lane & 7) + 8 * ((lane >> 3) & 1);
        int coff = (lane >> 4) & 1;
        #pragma unroll
        for (int kc = 0; kc < 8; ++kc)
            ldm4(xa[kc], smb + QOFF_X +
                 (uint32_t)(xrow * 256 + swz(2 * kc + coff, xrow) * 16));
    }

    const int vrl = (lane & 7) + 8 * ((lane >> 3) & 1);
    const int vco = (lane >> 4) & 1;
    const float* bvec[3] = {bq, bk, bv};
    __half* omat[3];
    omat[0] = g_q; omat[1] = g_k; omat[2] = g_v;

    #pragma unroll
    for (int m = 0; m < 3; ++m) {
        const uint32_t wb = smb + QOFF_W + (uint32_t)m * 32768u;
        float oacc[16][4];
        #pragma unroll
        for (int j = 0; j < 16; ++j)
            #pragma unroll
            for (int e = 0; e < 4; ++e) oacc[j][e] = 0.f;

        #pragma unroll
        for (int n2 = 0; n2 < 8; ++n2) {
            #pragma unroll
            for (int kc = 0; kc < 8; ++kc) {
                uint32_t wr[4];
                int ci = 16 * kc + vrl;
                int c = 2 * n2 + vco;
                ldm4t(wr, wb + (uint32_t)(ci * 256 + swz(c, ci) * 16));
                mma_f32(oacc[2 * n2],     xa[kc], wr[0], wr[1]);
                mma_f32(oacc[2 * n2 + 1], xa[kc], wr[2], wr[3]);
            }
        }

        const float qs = (m == 0) ? 0.08838834764831845f : 1.0f;  // 1/sqrt(128)
        __half* o = omat[m];
        const int r0 = tok0 + 16 * wid + g;
        #pragma unroll
        for (int j = 0; j < 16; ++j) {
            int col = 8 * j + 2 * tg;
            float b0 = bvec[m][col], b1 = bvec[m][col + 1];
            uint32_t p0 = packh((oacc[j][1] + b1) * qs, (oacc[j][0] + b0) * qs);
            uint32_t p1 = packh((oacc[j][3] + b1) * qs, (oacc[j][2] + b0) * qs);
            *(uint32_t*)(o + (size_t)r0 * CCH + col)       = p0;
            *(uint32_t*)(o + (size_t)(r0 + 8) * CCH + col) = p1;
        }
    }
}

// ---------------------------------------------------------------------------
// Kernel 2: FA2 attention, f16 pipeline, 4 warps x 32 q-rows.
// Each warp owns 2 row-groups (16 rows each) sharing every K/V fragment load
// (halves B-fragment LDS vs 16-row warps). S: f32 accum; PV: f16 accum.
// Keys processed in 32-key chunks to bound sacc registers.
// SMEM: Q 32KB @0, K 2x32KB @32768, V 2x32KB @98304 (163840 B).
// ---------------------------------------------------------------------------
#define OFF_Q 0u
#define OFF_K 32768u
#define OFF_V 98304u
#define A_SMEM 163840

__global__ __launch_bounds__(128, 1) void attn_mma(
    const float* __restrict__ x, float* __restrict__ out)
{
    uint32_t smb = smem_u32(dyn_smem);
    const int tid = threadIdx.x, wid = tid >> 5, lane = tid & 31;
    const int g = lane >> 2, tg = lane & 3;
    const int b = blockIdx.y, q0 = blockIdx.x * TILE;

    const __half* gq = g_q + (size_t)(b * NTOK + q0) * CCH;
    const __half* gk = g_k + (size_t)b * NTOK * CCH;
    const __half* gv = g_v + (size_t)b * NTOK * CCH;

    // ---- initial loads: Q, K0, V0 (swizzled 16B chunks), 128 threads ----
    #pragma unroll
    for (int it = 0; it < 16; ++it) {
        int idx = it * 128 + tid;
        int row = idx >> 4, c = idx & 15;
        uint32_t so = (uint32_t)(row * 256 + swz(c, row) * 16);
        cp16(smb + OFF_Q + so, (const char*)gq + idx * 16);
        cp16(smb + OFF_K + so, (const char*)gk + idx * 16);
        cp16(smb + OFF_V + so, (const char*)gv + idx * 16);
    }
    cp_commit();
    cp_wait_all();
    __syncthreads();

    // ---- Q fragments: 2 row-groups x 8 k-chunks (persist) ----
    uint32_t qa[2][8][4];
    #pragma unroll
    for (int rg = 0; rg < 2; ++rg) {
        int qrow = 32 * wid + 16 * rg + (lane & 7) + 8 * ((lane >> 3) & 1);
        int coff = (lane >> 4) & 1;
        #pragma unroll
        for (int kc = 0; kc < 8; ++kc)
            ldm4(qa[rg][kc], smb + OFF_Q +
                 (uint32_t)(qrow * 256 + swz(2 * kc + coff, qrow) * 16));
    }

    uint32_t oacc[2][16][2];   // f16x2 accumulators
    #pragma unroll
    for (int rg = 0; rg < 2; ++rg)
        #pragma unroll
        for (int j = 0; j < 16; ++j) { oacc[rg][j][0] = 0u; oacc[rg][j][1] = 0u; }
    float rs[2][2] = {{0.f, 0.f}, {0.f, 0.f}};

    const int krl = (lane & 7) + 8 * ((lane >> 4) & 1);
    const int kco = (lane >> 3) & 1;
    const int vrl = (lane & 7) + 8 * ((lane >> 3) & 1);
    const int vco = (lane >> 4) & 1;

    for (int kt = 0; kt < NT; ++kt) {
        const uint32_t kb = smb + OFF_K + (uint32_t)(kt & 1) * 32768u;
        const uint32_t vb = smb + OFF_V + (uint32_t)(kt & 1) * 32768u;

        // prefetch next tile
        if (kt + 1 < NT) {
            const char* kk = (const char*)(gk + (size_t)(kt + 1) * TILE * CCH);
            const char* vv = (const char*)(gv + (size_t)(kt + 1) * TILE * CCH);
            uint32_t kb2 = smb + OFF_K + (uint32_t)((kt + 1) & 1) * 32768u;
            uint32_t vb2 = smb + OFF_V + (uint32_t)((kt + 1) & 1) * 32768u;
            #pragma unroll
            for (int it = 0; it < 16; ++it) {
                int idx = it * 128 + tid;
                int row = idx >> 4, c = idx & 15;
                uint32_t so = (uint32_t)(row * 256 + swz(c, row) * 16);
                cp16(kb2 + so, kk + idx * 16);
                cp16(vb2 + so, vv + idx * 16);
            }
            cp_commit();
        }

        // ---- key chunks of 32 ----
        #pragma unroll
        for (int c4 = 0; c4 < 4; ++c4) {
            // S = Q K^T for 32 keys, both row-groups
            float sacc[2][2][2][4];
            #pragma unroll
            for (int rg = 0; rg < 2; ++rg)
                #pragma unroll
                for (int kg2 = 0; kg2 < 2; ++kg2)
                    #pragma unroll
                    for (int h = 0; h < 2; ++h)
                        #pragma unroll
                        for (int e = 0; e < 4; ++e) sacc[rg][kg2][h][e] = 0.f;

            #pragma unroll
            for (int kc = 0; kc < 8; ++kc) {
                #pragma unroll
                for (int kg2 = 0; kg2 < 2; ++kg2) {
                    uint32_t kr[4];
                    int key = 16 * (2 * c4 + kg2) + krl;
                    int c = 2 * kc + kco;
                    ldm4(kr, kb + (uint32_t)(key * 256 + swz(c, key) * 16));
                    #pragma unroll
                    for (int rg = 0; rg < 2; ++rg) {
                        mma_f32(sacc[rg][kg2][0], qa[rg][kc], kr[0], kr[1]);
                        mma_f32(sacc[rg][kg2][1], qa[rg][kc], kr[2], kr[3]);
                    }
                }
            }

            // softmax (no max-sub) + pack P as f16 A-fragments
            uint32_t pa[2][2][4];
            #pragma unroll
            for (int rg = 0; rg < 2; ++rg) {
                #pragma unroll
                for (int kg2 = 0; kg2 < 2; ++kg2) {
                    float* s0 = sacc[rg][kg2][0];
                    float* s1 = sacc[rg][kg2][1];
                    #pragma unroll
                    for (int e = 0; e < 4; ++e) {
                        s0[e] = __expf(s0[e]); s1[e] = __expf(s1[e]);
                    }
                    rs[rg][0] += s0[0] + s0[1] + s1[0] + s1[1];
                    rs[rg][1] += s0[2] + s0[3] + s1[2] + s1[3];
                    pa[rg][kg2][0] = packh(s0[1], s0[0]);
                    pa[rg][kg2][1] = packh(s0[3], s0[2]);
                    pa[rg][kg2][2] = packh(s1[1], s1[0]);
                    pa[rg][kg2][3] = packh(s1[3], s1[2]);
                }
            }

            // PV accumulate (f16 acc): 32 keys x 128 out channels
            #pragma unroll
            for (int kg2 = 0; kg2 < 2; ++kg2) {
                int key = 16 * (2 * c4 + kg2) + vrl;
                #pragma unroll
                for (int n2 = 0; n2 < 8; ++n2) {
                    uint32_t vr[4];
                    int c = 2 * n2 + vco;
                    ldm4t(vr, vb + (uint32_t)(key * 256 + swz(c, key) * 16));
                    #pragma unroll
                    for (int rg = 0; rg < 2; ++rg) {
                        mma_f16(oacc[rg][2 * n2],     pa[rg][kg2], vr[0], vr[1]);
                        mma_f16(oacc[rg][2 * n2 + 1], pa[rg][kg2], vr[2], vr[3]);
                    }
                }
            }
        }

        if (kt + 1 < NT) cp_wait_all();
        __syncthreads();
    }

    // ---- rowsum reduce across quad threads ----
    #pragma unroll
    for (int rg = 0; rg < 2; ++rg)
        #pragma unroll
        for (int h = 0; h < 2; ++h) {
            rs[rg][h] += __shfl_xor_sync(0xffffffffu, rs[rg][h], 1);
            rs[rg][h] += __shfl_xor_sync(0xffffffffu, rs[rg][h], 2);
        }

    // ---- epilogue: out = x + acc / rowsum ----
    #pragma unroll
    for (int rg = 0; rg < 2; ++rg) {
        const float inv0 = 1.0f / rs[rg][0], inv1 = 1.0f / rs[rg][1];
        const int row0 = q0 + 32 * wid + 16 * rg + g;
        const size_t base0 = ((size_t)b * NTOK + row0) * CCH;
        const size_t base1 = base0 + 8 * CCH;
        #pragma unroll
        for (int j = 0; j < 16; ++j) {
            int col = 8 * j + 2 * tg;
            __half2 h0 = *reinterpret_cast<__half2*>(&oacc[rg][j][0]);
            __half2 h1 = *reinterpret_cast<__half2*>(&oacc[rg][j][1]);
            float2 f0 = __half22float2(h0);
            float2 f1 = __half22float2(h1);
            float2 x0 = *(const float2*)(x + base0 + col);
            float2 x1 = *(const float2*)(x + base1 + col);
            float2 o0 = {x0.x + f0.x * inv0, x0.y + f0.y * inv0};
            float2 o1 = {x1.x + f1.x * inv1, x1.y + f1.y * inv1};
            *(float2*)(out + base0 + col) = o0;
            *(float2*)(out + base1 + col) = o1;
        }
    }
}

// ---------------------------------------------------------------------------
extern "C" void kernel_launch(void* const* d_in, const int* in_sizes, int n_in,
                              void* d_out, int out_size)
{
    const float* x  = (const float*)d_in[0];
    const float* Wq = (const float*)d_in[1];
    const float* bq = (const float*)d_in[2];
    const float* Wk = (const float*)d_in[3];
    const float* bk = (const float*)d_in[4];
    const float* Wv = (const float*)d_in[5];
    const float* bv = (const float*)d_in[6];
    float* out = (float*)d_out;

    cudaFuncSetAttribute(qkv_mma,
                         cudaFuncAttributeMaxDynamicSharedMemorySize, QKV_SMEM);
    cudaFuncSetAttribute(attn_mma,
                         cudaFuncAttributeMaxDynamicSharedMemorySize, A_SMEM);

    qkv_mma<<<TOKENS_ALL / 128, 256, QKV_SMEM>>>(x, Wq, bq, Wk, bk, Wv, bv);
    attn_mma<<<dim3(NTOK / TILE, BTOT), 128, A_SMEM>>>(x, out);
}

// round 8
// speedup vs baseline: 1.1016x; 1.1016x over previous
#include <cuda_runtime.h>
#include <cuda_fp16.h>
#include <cstdint>

#define BTOT 4
#define NTOK 4096
#define CCH  128
#define TOKENS_ALL (BTOT * NTOK)
#define TILE 128
#define NT (NTOK / TILE)

// f16 scratch for projected q (pre-scaled by 1/sqrt(C)), k, v
__device__ __half g_q[TOKENS_ALL * CCH];
__device__ __half g_k[TOKENS_ALL * CCH];
__device__ __half g_v[TOKENS_ALL * CCH];

extern __shared__ char dyn_smem[];

// ---------------------------------------------------------------------------
// helpers
// ---------------------------------------------------------------------------
__device__ __forceinline__ uint32_t smem_u32(const void* p) {
    uint32_t a;
    asm("{ .reg .u64 t; cvta.to.shared.u64 t, %1; cvt.u32.u64 %0, t; }"
        : "=r"(a) : "l"(p));
    return a;
}
__device__ __forceinline__ void cp16(uint32_t dst, const void* src) {
    asm volatile("cp.async.cg.shared.global [%0], [%1], 16;"
                 :: "r"(dst), "l"(src) : "memory");
}
__device__ __forceinline__ void cp_commit() {
    asm volatile("cp.async.commit_group;" ::: "memory");
}
__device__ __forceinline__ void cp_wait_all() {
    asm volatile("cp.async.wait_group 0;" ::: "memory");
}
__device__ __forceinline__ void ldm4(uint32_t (&r)[4], uint32_t a) {
    asm volatile("ldmatrix.sync.aligned.m8n8.x4.shared.b16 {%0,%1,%2,%3}, [%4];"
                 : "=r"(r[0]), "=r"(r[1]), "=r"(r[2]), "=r"(r[3]) : "r"(a));
}
__device__ __forceinline__ void ldm4t(uint32_t (&r)[4], uint32_t a) {
    asm volatile("ldmatrix.sync.aligned.m8n8.x4.trans.shared.b16 {%0,%1,%2,%3}, [%4];"
                 : "=r"(r[0]), "=r"(r[1]), "=r"(r[2]), "=r"(r[3]) : "r"(a));
}
// f16 inputs, f32 accumulators
__device__ __forceinline__ void mma_f32(float (&d)[4], const uint32_t (&a)[4],
                                        uint32_t b0, uint32_t b1) {
    asm volatile(
        "mma.sync.aligned.m16n8k16.row.col.f32.f16.f16.f32 "
        "{%0,%1,%2,%3}, {%4,%5,%6,%7}, {%8,%9}, {%0,%1,%2,%3};"
        : "+f"(d[0]), "+f"(d[1]), "+f"(d[2]), "+f"(d[3])
        : "r"(a[0]), "r"(a[1]), "r"(a[2]), "r"(a[3]), "r"(b0), "r"(b1));
}
// f16 inputs, f16 accumulators (2 packed regs)
__device__ __forceinline__ void mma_f16(uint32_t (&d)[2], const uint32_t (&a)[4],
                                        uint32_t b0, uint32_t b1) {
    asm volatile(
        "mma.sync.aligned.m16n8k16.row.col.f16.f16.f16.f16 "
        "{%0,%1}, {%2,%3,%4,%5}, {%6,%7}, {%0,%1};"
        : "+r"(d[0]), "+r"(d[1])
        : "r"(a[0]), "r"(a[1]), "r"(a[2]), "r"(a[3]), "r"(b0), "r"(b1));
}
__device__ __forceinline__ uint32_t packh(float hi, float lo) {
    __half2 h = __floats2half2_rn(lo, hi);   // x = lo, y = hi
    return *reinterpret_cast<uint32_t*>(&h);
}
__device__ __forceinline__ void sts128(uint32_t a, uint32_t r0, uint32_t r1,
                                       uint32_t r2, uint32_t r3) {
    asm volatile("st.shared.v4.b32 [%0], {%1,%2,%3,%4};"
                 :: "r"(a), "r"(r0), "r"(r1), "r"(r2), "r"(r3) : "memory");
}
// 16B-chunk swizzle within a 256B row: conflict-free ldmatrix + cp.async
__device__ __forceinline__ int swz(int c, int r) {
    return (c & 8) | ((c ^ r) & 7);
}

// ---------------------------------------------------------------------------
// Kernel 1: fused QKV projection on mma.sync f16 (f32 accum) — R6/R7 proven.
// ---------------------------------------------------------------------------
#define QOFF_X 0u
#define QOFF_W 32768u
#define QKV_SMEM (32768 * 4)

__global__ __launch_bounds__(256, 1) void qkv_mma(
    const float* __restrict__ x,
    const float* __restrict__ Wq, const float* __restrict__ bq,
    const float* __restrict__ Wk, const float* __restrict__ bk,
    const float* __restrict__ Wv, const float* __restrict__ bv)
{
    uint32_t smb = smem_u32(dyn_smem);
    const int tid = threadIdx.x, wid = tid >> 5, lane = tid & 31;
    const int g = lane >> 2, tg = lane & 3;
    const int tok0 = blockIdx.x * 128;

    #pragma unroll
    for (int it = 0; it < 8; ++it) {
        int idx = it * 256 + tid;
        int row = idx >> 4, c = idx & 15;
        const float* src = x + (size_t)(tok0 + row) * CCH + 8 * c;
        float4 a = *(const float4*)src;
        float4 b2 = *(const float4*)(src + 4);
        uint32_t dst = smb + QOFF_X + (uint32_t)(row * 256 + swz(c, row) * 16);
        sts128(dst, packh(a.y, a.x), packh(a.w, a.z),
                    packh(b2.y, b2.x), packh(b2.w, b2.z));
    }
    const float* Wmat[3] = {Wq, Wk, Wv};
    #pragma unroll
    for (int m = 0; m < 3; ++m) {
        #pragma unroll
        for (int it = 0; it < 8; ++it) {
            int idx = it * 256 + tid;
            int row = idx >> 4, c = idx & 15;
            const float* src = Wmat[m] + (size_t)row * CCH + 8 * c;
            float4 a = *(const float4*)src;
            float4 b2 = *(const float4*)(src + 4);
            uint32_t dst = smb + QOFF_W + (uint32_t)m * 32768u +
                           (uint32_t)(row * 256 + swz(c, row) * 16);
            sts128(dst, packh(a.y, a.x), packh(a.w, a.z),
                        packh(b2.y, b2.x), packh(b2.w, b2.z));
        }
    }
    __syncthreads();

    uint32_t xa[8][4];
    {
        int xrow = 16 * wid + (lane & 7) + 8 * ((lane >> 3) & 1);
        int coff = (lane >> 4) & 1;
        #pragma unroll
        for (int kc = 0; kc < 8; ++kc)
            ldm4(xa[kc], smb + QOFF_X +
                 (uint32_t)(xrow * 256 + swz(2 * kc + coff, xrow) * 16));
    }

    const int vrl = (lane & 7) + 8 * ((lane >> 3) & 1);
    const int vco = (lane >> 4) & 1;
    const float* bvec[3] = {bq, bk, bv};
    __half* omat[3];
    omat[0] = g_q; omat[1] = g_k; omat[2] = g_v;

    #pragma unroll
    for (int m = 0; m < 3; ++m) {
        const uint32_t wb = smb + QOFF_W + (uint32_t)m * 32768u;
        float oacc[16][4];
        #pragma unroll
        for (int j = 0; j < 16; ++j)
            #pragma unroll
            for (int e = 0; e < 4; ++e) oacc[j][e] = 0.f;

        #pragma unroll
        for (int n2 = 0; n2 < 8; ++n2) {
            #pragma unroll
            for (int kc = 0; kc < 8; ++kc) {
                uint32_t wr[4];
                int ci = 16 * kc + vrl;
                int c = 2 * n2 + vco;
                ldm4t(wr, wb + (uint32_t)(ci * 256 + swz(c, ci) * 16));
                mma_f32(oacc[2 * n2],     xa[kc], wr[0], wr[1]);
                mma_f32(oacc[2 * n2 + 1], xa[kc], wr[2], wr[3]);
            }
        }

        const float qs = (m == 0) ? 0.08838834764831845f : 1.0f;  // 1/sqrt(128)
        __half* o = omat[m];
        const int r0 = tok0 + 16 * wid + g;
        #pragma unroll
        for (int j = 0; j < 16; ++j) {
            int col = 8 * j + 2 * tg;
            float b0 = bvec[m][col], b1 = bvec[m][col + 1];
            uint32_t p0 = packh((oacc[j][1] + b1) * qs, (oacc[j][0] + b0) * qs);
            uint32_t p1 = packh((oacc[j][3] + b1) * qs, (oacc[j][2] + b0) * qs);
            *(uint32_t*)(o + (size_t)r0 * CCH + col)       = p0;
            *(uint32_t*)(o + (size_t)(r0 + 8) * CCH + col) = p1;
        }
    }
}

// ---------------------------------------------------------------------------
// Kernel 2: FA2 attention, f16 pipeline, 8 warps, split-key.
// Warp w: q-rows [32*(w&3), +32), keys [64*(w>>2), +64) of each 128-key tile.
// 32 rows/warp -> every K/V fragment feeds 2 row-groups (half the LDS of R6)
// at full 8-warp occupancy. Partial O / rowsum combined across the two key
// halves through SMEM at the end.
// SMEM: Q 32KB @0, K 2x32KB @32768, V 2x32KB @98304 (163840 B).
// Epilogue staging reuses bytes [0..33280).
// ---------------------------------------------------------------------------
#define OFF_Q 0u
#define OFF_K 32768u
#define OFF_V 98304u
#define A_SMEM 163840

__global__ __launch_bounds__(256, 1) void attn_mma(
    const float* __restrict__ x, float* __restrict__ out)
{
    uint32_t smb = smem_u32(dyn_smem);
    const int tid = threadIdx.x, wid = tid >> 5, lane = tid & 31;
    const int g = lane >> 2, tg = lane & 3;
    const int rowgrp = wid & 3;          // 32-row group
    const int keyhalf = wid >> 2;        // 64-key half
    const int b = blockIdx.y, q0 = blockIdx.x * TILE;

    const __half* gq = g_q + (size_t)(b * NTOK + q0) * CCH;
    const __half* gk = g_k + (size_t)b * NTOK * CCH;
    const __half* gv = g_v + (size_t)b * NTOK * CCH;

    // ---- initial loads: Q, K0, V0 (swizzled 16B chunks) ----
    #pragma unroll
    for (int it = 0; it < 8; ++it) {
        int idx = it * 256 + tid;
        int row = idx >> 4, c = idx & 15;
        uint32_t so = (uint32_t)(row * 256 + swz(c, row) * 16);
        cp16(smb + OFF_Q + so, (const char*)gq + idx * 16);
        cp16(smb + OFF_K + so, (const char*)gk + idx * 16);
        cp16(smb + OFF_V + so, (const char*)gv + idx * 16);
    }
    cp_commit();
    cp_wait_all();
    __syncthreads();

    // ---- Q fragments: 2 row-groups x 8 k-chunks (persist) ----
    uint32_t qa[2][8][4];
    #pragma unroll
    for (int rg = 0; rg < 2; ++rg) {
        int qrow = 32 * rowgrp + 16 * rg + (lane & 7) + 8 * ((lane >> 3) & 1);
        int coff = (lane >> 4) & 1;
        #pragma unroll
        for (int kc = 0; kc < 8; ++kc)
            ldm4(qa[rg][kc], smb + OFF_Q +
                 (uint32_t)(qrow * 256 + swz(2 * kc + coff, qrow) * 16));
    }

    uint32_t oacc[2][16][2];   // f16x2 accumulators
    #pragma unroll
    for (int rg = 0; rg < 2; ++rg)
        #pragma unroll
        for (int j = 0; j < 16; ++j) { oacc[rg][j][0] = 0u; oacc[rg][j][1] = 0u; }
    float rs[2][2] = {{0.f, 0.f}, {0.f, 0.f}};

    const int krl = (lane & 7) + 8 * ((lane >> 4) & 1);
    const int kco = (lane >> 3) & 1;
    const int vrl = (lane & 7) + 8 * ((lane >> 3) & 1);
    const int vco = (lane >> 4) & 1;

    for (int kt = 0; kt < NT; ++kt) {
        const uint32_t kb = smb + OFF_K + (uint32_t)(kt & 1) * 32768u;
        const uint32_t vb = smb + OFF_V + (uint32_t)(kt & 1) * 32768u;

        // prefetch next tile
        if (kt + 1 < NT) {
            const char* kk = (const char*)(gk + (size_t)(kt + 1) * TILE * CCH);
            const char* vv = (const char*)(gv + (size_t)(kt + 1) * TILE * CCH);
            uint32_t kb2 = smb + OFF_K + (uint32_t)((kt + 1) & 1) * 32768u;
            uint32_t vb2 = smb + OFF_V + (uint32_t)((kt + 1) & 1) * 32768u;
            #pragma unroll
            for (int it = 0; it < 8; ++it) {
                int idx = it * 256 + tid;
                int row = idx >> 4, c = idx & 15;
                uint32_t so = (uint32_t)(row * 256 + swz(c, row) * 16);
                cp16(kb2 + so, kk + idx * 16);
                cp16(vb2 + so, vv + idx * 16);
            }
            cp_commit();
        }

        // ---- this warp's 64 keys, in 2 chunks of 32 ----
        #pragma unroll
        for (int c4 = 0; c4 < 2; ++c4) {
            const int keybase = 64 * keyhalf + 32 * c4;

            float sacc[2][2][2][4];
            #pragma unroll
            for (int rg = 0; rg < 2; ++rg)
                #pragma unroll
                for (int kg2 = 0; kg2 < 2; ++kg2)
                    #pragma unroll
                    for (int h = 0; h < 2; ++h)
                        #pragma unroll
                        for (int e = 0; e < 4; ++e) sacc[rg][kg2][h][e] = 0.f;

            #pragma unroll
            for (int kc = 0; kc < 8; ++kc) {
                #pragma unroll
                for (int kg2 = 0; kg2 < 2; ++kg2) {
                    uint32_t kr[4];
                    int key = keybase + 16 * kg2 + krl;
                    int c = 2 * kc + kco;
                    ldm4(kr, kb + (uint32_t)(key * 256 + swz(c, key) * 16));
                    #pragma unroll
                    for (int rg = 0; rg < 2; ++rg) {
                        mma_f32(sacc[rg][kg2][0], qa[rg][kc], kr[0], kr[1]);
                        mma_f32(sacc[rg][kg2][1], qa[rg][kc], kr[2], kr[3]);
                    }
                }
            }

            // softmax (no max-sub) + pack P as f16 A-fragments
            uint32_t pa[2][2][4];
            #pragma unroll
            for (int rg = 0; rg < 2; ++rg) {
                #pragma unroll
                for (int kg2 = 0; kg2 < 2; ++kg2) {
                    float* s0 = sacc[rg][kg2][0];
                    float* s1 = sacc[rg][kg2][1];
                    #pragma unroll
                    for (int e = 0; e < 4; ++e) {
                        s0[e] = __expf(s0[e]); s1[e] = __expf(s1[e]);
                    }
                    rs[rg][0] += s0[0] + s0[1] + s1[0] + s1[1];
                    rs[rg][1] += s0[2] + s0[3] + s1[2] + s1[3];
                    pa[rg][kg2][0] = packh(s0[1], s0[0]);
                    pa[rg][kg2][1] = packh(s0[3], s0[2]);
                    pa[rg][kg2][2] = packh(s1[1], s1[0]);
                    pa[rg][kg2][3] = packh(s1[3], s1[2]);
                }
            }

            // PV accumulate (f16 acc): 32 keys x 128 out channels
            #pragma unroll
            for (int kg2 = 0; kg2 < 2; ++kg2) {
                int key = keybase + 16 * kg2 + vrl;
                #pragma unroll
                for (int n2 = 0; n2 < 8; ++n2) {
                    uint32_t vr[4];
                    int c = 2 * n2 + vco;
                    ldm4t(vr, vb + (uint32_t)(key * 256 + swz(c, key) * 16));
                    #pragma unroll
                    for (int rg = 0; rg < 2; ++rg) {
                        mma_f16(oacc[rg][2 * n2],     pa[rg][kg2], vr[0], vr[1]);
                        mma_f16(oacc[rg][2 * n2 + 1], pa[rg][kg2], vr[2], vr[3]);
                    }
                }
            }
        }

        if (kt + 1 < NT) cp_wait_all();
        __syncthreads();
    }

    // ---- rowsum reduce across quad threads ----
    #pragma unroll
    for (int rg = 0; rg < 2; ++rg)
        #pragma unroll
        for (int h = 0; h < 2; ++h) {
            rs[rg][h] += __shfl_xor_sync(0xffffffffu, rs[rg][h], 1);
            rs[rg][h] += __shfl_xor_sync(0xffffffffu, rs[rg][h], 2);
        }

    // ---- combine key halves through SMEM ----
    // o-partials (f16x2) at [0, 32768); rowsums (f32) at [32768, 33280)
    __syncthreads();
    float* rsbuf = (float*)dyn_smem + 8192;
    if (keyhalf == 1) {
        #pragma unroll
        for (int rg = 0; rg < 2; ++rg) {
            int r0 = 32 * rowgrp + 16 * rg + g;
            #pragma unroll
            for (int j = 0; j < 16; ++j) {
                int col = 8 * j + 2 * tg;
                *(uint32_t*)(dyn_smem + (r0 * 128 + col) * 2)       = oacc[rg][j][0];
                *(uint32_t*)(dyn_smem + ((r0 + 8) * 128 + col) * 2) = oacc[rg][j][1];
            }
            if (tg == 0) {
                rsbuf[r0]     = rs[rg][0];
                rsbuf[r0 + 8] = rs[rg][1];
            }
        }
    }
    __syncthreads();

    if (keyhalf == 0) {
        #pragma unroll
        for (int rg = 0; rg < 2; ++rg) {
            int r0 = 32 * rowgrp + 16 * rg + g;
            const float inv0 = 1.0f / (rs[rg][0] + rsbuf[r0]);
            const float inv1 = 1.0f / (rs[rg][1] + rsbuf[r0 + 8]);
            const size_t base0 = ((size_t)b * NTOK + q0 + r0) * CCH;
            const size_t base1 = base0 + 8 * CCH;
            #pragma unroll
            for (int j = 0; j < 16; ++j) {
                int col = 8 * j + 2 * tg;
                uint32_t q0u = *(uint32_t*)(dyn_smem + (r0 * 128 + col) * 2);
                uint32_t q1u = *(uint32_t*)(dyn_smem + ((r0 + 8) * 128 + col) * 2);
                __half2 m0 = *reinterpret_cast<__half2*>(&oacc[rg][j][0]);
                __half2 m1 = *reinterpret_cast<__half2*>(&oacc[rg][j][1]);
                __half2 p0 = *reinterpret_cast<__half2*>(&q0u);
                __half2 p1 = *reinterpret_cast<__half2*>(&q1u);
                float2 f0 = __half22float2(m0), e0 = __half22float2(p0);
                float2 f1 = __half22float2(m1), e1 = __half22float2(p1);
                float2 x0 = *(const float2*)(x + base0 + col);
                float2 x1 = *(const float2*)(x + base1 + col);
                float2 o0 = {x0.x + (f0.x + e0.x) * inv0,
                             x0.y + (f0.y + e0.y) * inv0};
                float2 o1 = {x1.x + (f1.x + e1.x) * inv1,
                             x1.y + (f1.y + e1.y) * inv1};
                *(float2*)(out + base0 + col) = o0;
                *(float2*)(out + base1 + col) = o1;
            }
        }
    }
}

// ---------------------------------------------------------------------------
extern "C" void kernel_launch(void* const* d_in, const int* in_sizes, int n_in,
                              void* d_out, int out_size)
{
    const float* x  = (const float*)d_in[0];
    const float* Wq = (const float*)d_in[1];
    const float* bq = (const float*)d_in[2];
    const float* Wk = (const float*)d_in[3];
    const float* bk = (const float*)d_in[4];
    const float* Wv = (const float*)d_in[5];
    const float* bv = (const float*)d_in[6];
    float* out = (float*)d_out;

    cudaFuncSetAttribute(qkv_mma,
                         cudaFuncAttributeMaxDynamicSharedMemorySize, QKV_SMEM);
    cudaFuncSetAttribute(attn_mma,
                         cudaFuncAttributeMaxDynamicSharedMemorySize, A_SMEM);

    qkv_mma<<<TOKENS_ALL / 128, 256, QKV_SMEM>>>(x, Wq, bq, Wk, bk, Wv, bv);
    attn_mma<<<dim3(NTOK / TILE, BTOT), 256, A_SMEM>>>(x, out);
}

// round 9
// speedup vs baseline: 1.1055x; 1.0036x over previous
#include <cuda_runtime.h>
#include <cuda_fp16.h>
#include <cstdint>

#define BTOT 4
#define NTOK 4096
#define CCH  128
#define TOKENS_ALL (BTOT * NTOK)
#define TILE 128
#define NT (NTOK / TILE)

// f16 scratch for projected q (pre-scaled by 1/sqrt(C)), k, v
__device__ __half g_q[TOKENS_ALL * CCH];
__device__ __half g_k[TOKENS_ALL * CCH];
__device__ __half g_v[TOKENS_ALL * CCH];

extern __shared__ char dyn_smem[];

// ---------------------------------------------------------------------------
// helpers
// ---------------------------------------------------------------------------
__device__ __forceinline__ uint32_t smem_u32(const void* p) {
    uint32_t a;
    asm("{ .reg .u64 t; cvta.to.shared.u64 t, %1; cvt.u32.u64 %0, t; }"
        : "=r"(a) : "l"(p));
    return a;
}
__device__ __forceinline__ void cp16(uint32_t dst, const void* src) {
    asm volatile("cp.async.cg.shared.global [%0], [%1], 16;"
                 :: "r"(dst), "l"(src) : "memory");
}
__device__ __forceinline__ void cp_commit() {
    asm volatile("cp.async.commit_group;" ::: "memory");
}
__device__ __forceinline__ void cp_wait_all() {
    asm volatile("cp.async.wait_group 0;" ::: "memory");
}
__device__ __forceinline__ void ldm4(uint32_t (&r)[4], uint32_t a) {
    asm volatile("ldmatrix.sync.aligned.m8n8.x4.shared.b16 {%0,%1,%2,%3}, [%4];"
                 : "=r"(r[0]), "=r"(r[1]), "=r"(r[2]), "=r"(r[3]) : "r"(a));
}
__device__ __forceinline__ void ldm4t(uint32_t (&r)[4], uint32_t a) {
    asm volatile("ldmatrix.sync.aligned.m8n8.x4.trans.shared.b16 {%0,%1,%2,%3}, [%4];"
                 : "=r"(r[0]), "=r"(r[1]), "=r"(r[2]), "=r"(r[3]) : "r"(a));
}
// f16 inputs, f32 accumulators
__device__ __forceinline__ void mma_f32(float (&d)[4], const uint32_t (&a)[4],
                                        uint32_t b0, uint32_t b1) {
    asm volatile(
        "mma.sync.aligned.m16n8k16.row.col.f32.f16.f16.f32 "
        "{%0,%1,%2,%3}, {%4,%5,%6,%7}, {%8,%9}, {%0,%1,%2,%3};"
        : "+f"(d[0]), "+f"(d[1]), "+f"(d[2]), "+f"(d[3])
        : "r"(a[0]), "r"(a[1]), "r"(a[2]), "r"(a[3]), "r"(b0), "r"(b1));
}
// f16 inputs, f16 accumulators (2 packed regs)
__device__ __forceinline__ void mma_f16(uint32_t (&d)[2], const uint32_t (&a)[4],
                                        uint32_t b0, uint32_t b1) {
    asm volatile(
        "mma.sync.aligned.m16n8k16.row.col.f16.f16.f16.f16 "
        "{%0,%1}, {%2,%3,%4,%5}, {%6,%7}, {%0,%1};"
        : "+r"(d[0]), "+r"(d[1])
        : "r"(a[0]), "r"(a[1]), "r"(a[2]), "r"(a[3]), "r"(b0), "r"(b1));
}
__device__ __forceinline__ uint32_t packh(float hi, float lo) {
    __half2 h = __floats2half2_rn(lo, hi);   // x = lo, y = hi
    return *reinterpret_cast<uint32_t*>(&h);
}
__device__ __forceinline__ void sts128(uint32_t a, uint32_t r0, uint32_t r1,
                                       uint32_t r2, uint32_t r3) {
    asm volatile("st.shared.v4.b32 [%0], {%1,%2,%3,%4};"
                 :: "r"(a), "r"(r0), "r"(r1), "r"(r2), "r"(r3) : "memory");
}
// 16B-chunk swizzle within a 256B row: conflict-free ldmatrix + cp.async
__device__ __forceinline__ int swz(int c, int r) {
    return (c & 8) | ((c ^ r) & 7);
}

// ---------------------------------------------------------------------------
// Kernel 1: fused QKV projection on mma.sync f16 (f32 accum) — proven.
// ---------------------------------------------------------------------------
#define QOFF_X 0u
#define QOFF_W 32768u
#define QKV_SMEM (32768 * 4)

__global__ __launch_bounds__(256, 1) void qkv_mma(
    const float* __restrict__ x,
    const float* __restrict__ Wq, const float* __restrict__ bq,
    const float* __restrict__ Wk, const float* __restrict__ bk,
    const float* __restrict__ Wv, const float* __restrict__ bv)
{
    uint32_t smb = smem_u32(dyn_smem);
    const int tid = threadIdx.x, wid = tid >> 5, lane = tid & 31;
    const int g = lane >> 2, tg = lane & 3;
    const int tok0 = blockIdx.x * 128;

    #pragma unroll
    for (int it = 0; it < 8; ++it) {
        int idx = it * 256 + tid;
        int row = idx >> 4, c = idx & 15;
        const float* src = x + (size_t)(tok0 + row) * CCH + 8 * c;
        float4 a = *(const float4*)src;
        float4 b2 = *(const float4*)(src + 4);
        uint32_t dst = smb + QOFF_X + (uint32_t)(row * 256 + swz(c, row) * 16);
        sts128(dst, packh(a.y, a.x), packh(a.w, a.z),
                    packh(b2.y, b2.x), packh(b2.w, b2.z));
    }
    const float* Wmat[3] = {Wq, Wk, Wv};
    #pragma unroll
    for (int m = 0; m < 3; ++m) {
        #pragma unroll
        for (int it = 0; it < 8; ++it) {
            int idx = it * 256 + tid;
            int row = idx >> 4, c = idx & 15;
            const float* src = Wmat[m] + (size_t)row * CCH + 8 * c;
            float4 a = *(const float4*)src;
            float4 b2 = *(const float4*)(src + 4);
            uint32_t dst = smb + QOFF_W + (uint32_t)m * 32768u +
                           (uint32_t)(row * 256 + swz(c, row) * 16);
            sts128(dst, packh(a.y, a.x), packh(a.w, a.z),
                        packh(b2.y, b2.x), packh(b2.w, b2.z));
        }
    }
    __syncthreads();

    uint32_t xa[8][4];
    {
        int xrow = 16 * wid + (lane & 7) + 8 * ((lane >> 3) & 1);
        int coff = (lane >> 4) & 1;
        #pragma unroll
        for (int kc = 0; kc < 8; ++kc)
            ldm4(xa[kc], smb + QOFF_X +
                 (uint32_t)(xrow * 256 + swz(2 * kc + coff, xrow) * 16));
    }

    const int vrl = (lane & 7) + 8 * ((lane >> 3) & 1);
    const int vco = (lane >> 4) & 1;
    const float* bvec[3] = {bq, bk, bv};
    __half* omat[3];
    omat[0] = g_q; omat[1] = g_k; omat[2] = g_v;

    #pragma unroll
    for (int m = 0; m < 3; ++m) {
        const uint32_t wb = smb + QOFF_W + (uint32_t)m * 32768u;
        float oacc[16][4];
        #pragma unroll
        for (int j = 0; j < 16; ++j)
            #pragma unroll
            for (int e = 0; e < 4; ++e) oacc[j][e] = 0.f;

        #pragma unroll
        for (int n2 = 0; n2 < 8; ++n2) {
            #pragma unroll
            for (int kc = 0; kc < 8; ++kc) {
                uint32_t wr[4];
                int ci = 16 * kc + vrl;
                int c = 2 * n2 + vco;
                ldm4t(wr, wb + (uint32_t)(ci * 256 + swz(c, ci) * 16));
                mma_f32(oacc[2 * n2],     xa[kc], wr[0], wr[1]);
                mma_f32(oacc[2 * n2 + 1], xa[kc], wr[2], wr[3]);
            }
        }

        const float qs = (m == 0) ? 0.08838834764831845f : 1.0f;  // 1/sqrt(128)
        __half* o = omat[m];
        const int r0 = tok0 + 16 * wid + g;
        #pragma unroll
        for (int j = 0; j < 16; ++j) {
            int col = 8 * j + 2 * tg;
            float b0 = bvec[m][col], b1 = bvec[m][col + 1];
            uint32_t p0 = packh((oacc[j][1] + b1) * qs, (oacc[j][0] + b0) * qs);
            uint32_t p1 = packh((oacc[j][3] + b1) * qs, (oacc[j][2] + b0) * qs);
            *(uint32_t*)(o + (size_t)r0 * CCH + col)       = p0;
            *(uint32_t*)(o + (size_t)(r0 + 8) * CCH + col) = p1;
        }
    }
}

// ---------------------------------------------------------------------------
// Kernel 2: FA2 attention — R5 chassis (8 warps x 16 q-rows), full f16-acc.
// S and PV both use m16n8k16 f16 accumulators. The f16 C-fragment of S is
// layout-identical to the A-fragment PV needs, so P = h2exp(S) in place,
// no repacking. Rowsums accumulated in f32 from unpacked P.
// SMEM: Q 32KB @0, K 2x32KB @32768, V 2x32KB @98304 (163840 B).
// ---------------------------------------------------------------------------
#define OFF_Q 0u
#define OFF_K 32768u
#define OFF_V 98304u
#define A_SMEM 163840

__global__ __launch_bounds__(256, 1) void attn_mma(
    const float* __restrict__ x, float* __restrict__ out)
{
    uint32_t smb = smem_u32(dyn_smem);
    const int tid = threadIdx.x, wid = tid >> 5, lane = tid & 31;
    const int g = lane >> 2, tg = lane & 3;
    const int b = blockIdx.y, q0 = blockIdx.x * TILE;

    const __half* gq = g_q + (size_t)(b * NTOK + q0) * CCH;
    const __half* gk = g_k + (size_t)b * NTOK * CCH;
    const __half* gv = g_v + (size_t)b * NTOK * CCH;

    #pragma unroll
    for (int it = 0; it < 8; ++it) {
        int idx = it * 256 + tid;
        int row = idx >> 4, c = idx & 15;
        uint32_t so = (uint32_t)(row * 256 + swz(c, row) * 16);
        cp16(smb + OFF_Q + so, (const char*)gq + idx * 16);
        cp16(smb + OFF_K + so, (const char*)gk + idx * 16);
        cp16(smb + OFF_V + so, (const char*)gv + idx * 16);
    }
    cp_commit();
    cp_wait_all();
    __syncthreads();

    // Q fragments (persist)
    uint32_t qa[8][4];
    {
        int qrow = 16 * wid + (lane & 7) + 8 * ((lane >> 3) & 1);
        int coff = (lane >> 4) & 1;
        #pragma unroll
        for (int kc = 0; kc < 8; ++kc)
            ldm4(qa[kc], smb + OFF_Q +
                 (uint32_t)(qrow * 256 + swz(2 * kc + coff, qrow) * 16));
    }

    uint32_t oacc[16][2];     // f16x2 accumulators
    #pragma unroll
    for (int j = 0; j < 16; ++j) { oacc[j][0] = 0u; oacc[j][1] = 0u; }
    float rs0 = 0.f, rs1 = 0.f;

    const int krl = (lane & 7) + 8 * ((lane >> 4) & 1);
    const int kco = (lane >> 3) & 1;
    const int vrl = (lane & 7) + 8 * ((lane >> 3) & 1);
    const int vco = (lane >> 4) & 1;

    for (int kt = 0; kt < NT; ++kt) {
        const uint32_t kb = smb + OFF_K + (uint32_t)(kt & 1) * 32768u;
        const uint32_t vb = smb + OFF_V + (uint32_t)(kt & 1) * 32768u;

        if (kt + 1 < NT) {
            const char* kk = (const char*)(gk + (size_t)(kt + 1) * TILE * CCH);
            const char* vv = (const char*)(gv + (size_t)(kt + 1) * TILE * CCH);
            uint32_t kb2 = smb + OFF_K + (uint32_t)((kt + 1) & 1) * 32768u;
            uint32_t vb2 = smb + OFF_V + (uint32_t)((kt + 1) & 1) * 32768u;
            #pragma unroll
            for (int it = 0; it < 8; ++it) {
                int idx = it * 256 + tid;
                int row = idx >> 4, c = idx & 15;
                uint32_t so = (uint32_t)(row * 256 + swz(c, row) * 16);
                cp16(kb2 + so, kk + idx * 16);
                cp16(vb2 + so, vv + idx * 16);
            }
            cp_commit();
        }

        // ---- S = Q K^T, f16 accumulate ----
        uint32_t sacc[16][2];
        #pragma unroll
        for (int j = 0; j < 16; ++j) { sacc[j][0] = 0u; sacc[j][1] = 0u; }

        #pragma unroll
        for (int n2 = 0; n2 < 8; ++n2) {
            #pragma unroll
            for (int kc = 0; kc < 8; ++kc) {
                uint32_t kr[4];
                int key = 16 * n2 + krl;
                int c = 2 * kc + kco;
                ldm4(kr, kb + (uint32_t)(key * 256 + swz(c, key) * 16));
                mma_f16(sacc[2 * n2],     qa[kc], kr[0], kr[1]);
                mma_f16(sacc[2 * n2 + 1], qa[kc], kr[2], kr[3]);
            }
        }

        // ---- softmax in f16 fragments (no repack) + PV ----
        #pragma unroll
        for (int kc = 0; kc < 8; ++kc) {
            // P A-fragment for keys [16kc,16kc+16): direct from S fragments
            __half2 e00 = h2exp(*reinterpret_cast<__half2*>(&sacc[2 * kc][0]));
            __half2 e01 = h2exp(*reinterpret_cast<__half2*>(&sacc[2 * kc][1]));
            __half2 e10 = h2exp(*reinterpret_cast<__half2*>(&sacc[2 * kc + 1][0]));
            __half2 e11 = h2exp(*reinterpret_cast<__half2*>(&sacc[2 * kc + 1][1]));
            float2 f00 = __half22float2(e00), f01 = __half22float2(e01);
            float2 f10 = __half22float2(e10), f11 = __half22float2(e11);
            rs0 += f00.x + f00.y + f10.x + f10.y;   // row g
            rs1 += f01.x + f01.y + f11.x + f11.y;   // row g+8
            uint32_t pa[4] = { *reinterpret_cast<uint32_t*>(&e00),
                               *reinterpret_cast<uint32_t*>(&e01),
                               *reinterpret_cast<uint32_t*>(&e10),
                               *reinterpret_cast<uint32_t*>(&e11) };
            int key = 16 * kc + vrl;
            #pragma unroll
            for (int n2 = 0; n2 < 8; ++n2) {
                uint32_t vr[4];
                int c = 2 * n2 + vco;
                ldm4t(vr, vb + (uint32_t)(key * 256 + swz(c, key) * 16));
                mma_f16(oacc[2 * n2],     pa, vr[0], vr[1]);
                mma_f16(oacc[2 * n2 + 1], pa, vr[2], vr[3]);
            }
        }

        if (kt + 1 < NT) cp_wait_all();
        __syncthreads();
    }

    // ---- rowsum reduce across quad threads ----
    rs0 += __shfl_xor_sync(0xffffffffu, rs0, 1);
    rs0 += __shfl_xor_sync(0xffffffffu, rs0, 2);
    rs1 += __shfl_xor_sync(0xffffffffu, rs1, 1);
    rs1 += __shfl_xor_sync(0xffffffffu, rs1, 2);
    const float inv0 = 1.0f / rs0, inv1 = 1.0f / rs1;

    // ---- epilogue: out = x + acc / rowsum ----
    const int row0 = q0 + 16 * wid + g;
    const size_t base0 = ((size_t)b * NTOK + row0) * CCH;
    const size_t base1 = base0 + 8 * CCH;
    #pragma unroll
    for (int j = 0; j < 16; ++j) {
        int col = 8 * j + 2 * tg;
        __half2 h0 = *reinterpret_cast<__half2*>(&oacc[j][0]);
        __half2 h1 = *reinterpret_cast<__half2*>(&oacc[j][1]);
        float2 f0 = __half22float2(h0);
        float2 f1 = __half22float2(h1);
        float2 x0 = *(const float2*)(x + base0 + col);
        float2 x1 = *(const float2*)(x + base1 + col);
        float2 o0 = {x0.x + f0.x * inv0, x0.y + f0.y * inv0};
        float2 o1 = {x1.x + f1.x * inv1, x1.y + f1.y * inv1};
        *(float2*)(out + base0 + col) = o0;
        *(float2*)(out + base1 + col) = o1;
    }
}

// ---------------------------------------------------------------------------
extern "C" void kernel_launch(void* const* d_in, const int* in_sizes, int n_in,
                              void* d_out, int out_size)
{
    const float* x  = (const float*)d_in[0];
    const float* Wq = (const float*)d_in[1];
    const float* bq = (const float*)d_in[2];
    const float* Wk = (const float*)d_in[3];
    const float* bk = (const float*)d_in[4];
    const float* Wv = (const float*)d_in[5];
    const float* bv = (const float*)d_in[6];
    float* out = (float*)d_out;

    cudaFuncSetAttribute(qkv_mma,
                         cudaFuncAttributeMaxDynamicSharedMemorySize, QKV_SMEM);
    cudaFuncSetAttribute(attn_mma,
                         cudaFuncAttributeMaxDynamicSharedMemorySize, A_SMEM);

    qkv_mma<<<TOKENS_ALL / 128, 256, QKV_SMEM>>>(x, Wq, bq, Wk, bk, Wv, bv);
    attn_mma<<<dim3(NTOK / TILE, BTOT), 256, A_SMEM>>>(x, out);
}

// round 10
// speedup vs baseline: 1.1915x; 1.0778x over previous
#include <cuda_runtime.h>
#include <cuda_fp16.h>
#include <cstdint>

#define BTOT 4
#define NTOK 4096
#define CCH  128
#define TOKENS_ALL (BTOT * NTOK)
#define TILE 128
#define NT (NTOK / TILE)

// f16 scratch for projected q (pre-scaled by 1/sqrt(C)), k, v
__device__ __half g_q[TOKENS_ALL * CCH];
__device__ __half g_k[TOKENS_ALL * CCH];
__device__ __half g_v[TOKENS_ALL * CCH];

extern __shared__ char dyn_smem[];

// ---------------------------------------------------------------------------
// helpers
// ---------------------------------------------------------------------------
__device__ __forceinline__ uint32_t smem_u32(const void* p) {
    uint32_t a;
    asm("{ .reg .u64 t; cvta.to.shared.u64 t, %1; cvt.u32.u64 %0, t; }"
        : "=r"(a) : "l"(p));
    return a;
}
__device__ __forceinline__ void cp16(uint32_t dst, const void* src) {
    asm volatile("cp.async.cg.shared.global [%0], [%1], 16;"
                 :: "r"(dst), "l"(src) : "memory");
}
__device__ __forceinline__ void cp_commit() {
    asm volatile("cp.async.commit_group;" ::: "memory");
}
__device__ __forceinline__ void cp_wait_all() {
    asm volatile("cp.async.wait_group 0;" ::: "memory");
}
__device__ __forceinline__ void ldm4(uint32_t (&r)[4], uint32_t a) {
    asm volatile("ldmatrix.sync.aligned.m8n8.x4.shared.b16 {%0,%1,%2,%3}, [%4];"
                 : "=r"(r[0]), "=r"(r[1]), "=r"(r[2]), "=r"(r[3]) : "r"(a));
}
__device__ __forceinline__ void ldm4t(uint32_t (&r)[4], uint32_t a) {
    asm volatile("ldmatrix.sync.aligned.m8n8.x4.trans.shared.b16 {%0,%1,%2,%3}, [%4];"
                 : "=r"(r[0]), "=r"(r[1]), "=r"(r[2]), "=r"(r[3]) : "r"(a));
}
// f16 inputs, f32 accumulators
__device__ __forceinline__ void mma_f32(float (&d)[4], const uint32_t (&a)[4],
                                        uint32_t b0, uint32_t b1) {
    asm volatile(
        "mma.sync.aligned.m16n8k16.row.col.f32.f16.f16.f32 "
        "{%0,%1,%2,%3}, {%4,%5,%6,%7}, {%8,%9}, {%0,%1,%2,%3};"
        : "+f"(d[0]), "+f"(d[1]), "+f"(d[2]), "+f"(d[3])
        : "r"(a[0]), "r"(a[1]), "r"(a[2]), "r"(a[3]), "r"(b0), "r"(b1));
}
__device__ __forceinline__ uint32_t packh(float hi, float lo) {
    __half2 h = __floats2half2_rn(lo, hi);   // x = lo, y = hi
    return *reinterpret_cast<uint32_t*>(&h);
}
__device__ __forceinline__ void sts128(uint32_t a, uint32_t r0, uint32_t r1,
                                       uint32_t r2, uint32_t r3) {
    asm volatile("st.shared.v4.b32 [%0], {%1,%2,%3,%4};"
                 :: "r"(a), "r"(r0), "r"(r1), "r"(r2), "r"(r3) : "memory");
}
// 16B-chunk swizzle within a 256B row: conflict-free ldmatrix + cp.async
__device__ __forceinline__ int swz(int c, int r) {
    return (c & 8) | ((c ^ r) & 7);
}

// ---------------------------------------------------------------------------
// Kernel 1: fused QKV projection, mma.sync f16 / f32 accum.
// Loop order kc-outer/n2-inner: consecutive mmas hit distinct accumulators
// (dependency distance 16) instead of an 8-deep same-accumulator chain.
// ---------------------------------------------------------------------------
#define QOFF_X 0u
#define QOFF_W 32768u
#define QKV_SMEM (32768 * 4)

__global__ __launch_bounds__(256, 1) void qkv_mma(
    const float* __restrict__ x,
    const float* __restrict__ Wq, const float* __restrict__ bq,
    const float* __restrict__ Wk, const float* __restrict__ bk,
    const float* __restrict__ Wv, const float* __restrict__ bv)
{
    uint32_t smb = smem_u32(dyn_smem);
    const int tid = threadIdx.x, wid = tid >> 5, lane = tid & 31;
    const int g = lane >> 2, tg = lane & 3;
    const int tok0 = blockIdx.x * 128;

    #pragma unroll
    for (int it = 0; it < 8; ++it) {
        int idx = it * 256 + tid;
        int row = idx >> 4, c = idx & 15;
        const float* src = x + (size_t)(tok0 + row) * CCH + 8 * c;
        float4 a = *(const float4*)src;
        float4 b2 = *(const float4*)(src + 4);
        uint32_t dst = smb + QOFF_X + (uint32_t)(row * 256 + swz(c, row) * 16);
        sts128(dst, packh(a.y, a.x), packh(a.w, a.z),
                    packh(b2.y, b2.x), packh(b2.w, b2.z));
    }
    const float* Wmat[3] = {Wq, Wk, Wv};
    #pragma unroll
    for (int m = 0; m < 3; ++m) {
        #pragma unroll
        for (int it = 0; it < 8; ++it) {
            int idx = it * 256 + tid;
            int row = idx >> 4, c = idx & 15;
            const float* src = Wmat[m] + (size_t)row * CCH + 8 * c;
            float4 a = *(const float4*)src;
            float4 b2 = *(const float4*)(src + 4);
            uint32_t dst = smb + QOFF_W + (uint32_t)m * 32768u +
                           (uint32_t)(row * 256 + swz(c, row) * 16);
            sts128(dst, packh(a.y, a.x), packh(a.w, a.z),
                        packh(b2.y, b2.x), packh(b2.w, b2.z));
        }
    }
    __syncthreads();

    uint32_t xa[8][4];
    {
        int xrow = 16 * wid + (lane & 7) + 8 * ((lane >> 3) & 1);
        int coff = (lane >> 4) & 1;
        #pragma unroll
        for (int kc = 0; kc < 8; ++kc)
            ldm4(xa[kc], smb + QOFF_X +
                 (uint32_t)(xrow * 256 + swz(2 * kc + coff, xrow) * 16));
    }

    const int vrl = (lane & 7) + 8 * ((lane >> 3) & 1);
    const int vco = (lane >> 4) & 1;
    const float* bvec[3] = {bq, bk, bv};
    __half* omat[3];
    omat[0] = g_q; omat[1] = g_k; omat[2] = g_v;

    #pragma unroll
    for (int m = 0; m < 3; ++m) {
        const uint32_t wb = smb + QOFF_W + (uint32_t)m * 32768u;
        float oacc[16][4];
        #pragma unroll
        for (int j = 0; j < 16; ++j)
            #pragma unroll
            for (int e = 0; e < 4; ++e) oacc[j][e] = 0.f;

        #pragma unroll
        for (int kc = 0; kc < 8; ++kc) {      // kc outer: break dep chains
            #pragma unroll
            for (int n2 = 0; n2 < 8; ++n2) {
                uint32_t wr[4];
                int ci = 16 * kc + vrl;
                int c = 2 * n2 + vco;
                ldm4t(wr, wb + (uint32_t)(ci * 256 + swz(c, ci) * 16));
                mma_f32(oacc[2 * n2],     xa[kc], wr[0], wr[1]);
                mma_f32(oacc[2 * n2 + 1], xa[kc], wr[2], wr[3]);
            }
        }

        const float qs = (m == 0) ? 0.08838834764831845f : 1.0f;  // 1/sqrt(128)
        __half* o = omat[m];
        const int r0 = tok0 + 16 * wid + g;
        #pragma unroll
        for (int j = 0; j < 16; ++j) {
            int col = 8 * j + 2 * tg;
            float b0 = bvec[m][col], b1 = bvec[m][col + 1];
            uint32_t p0 = packh((oacc[j][1] + b1) * qs, (oacc[j][0] + b0) * qs);
            uint32_t p1 = packh((oacc[j][3] + b1) * qs, (oacc[j][2] + b0) * qs);
            *(uint32_t*)(o + (size_t)r0 * CCH + col)       = p0;
            *(uint32_t*)(o + (size_t)(r0 + 8) * CCH + col) = p1;
        }
    }
}

// ---------------------------------------------------------------------------
// Kernel 2: FA2 attention — R5 chassis (8 warps x 16 q-rows), fp16 inputs,
// f32 accumulators. S-loop reordered kc-outer/n2-inner so consecutive HMMAs
// hit 16 distinct accumulators (dep distance 16, chain hidden).
// SMEM: Q 32KB @0, K 2x32KB @32768, V 2x32KB @98304 (163840 B).
// ---------------------------------------------------------------------------
#define OFF_Q 0u
#define OFF_K 32768u
#define OFF_V 98304u
#define A_SMEM 163840

__global__ __launch_bounds__(256, 1) void attn_mma(
    const float* __restrict__ x, float* __restrict__ out)
{
    uint32_t smb = smem_u32(dyn_smem);
    const int tid = threadIdx.x, wid = tid >> 5, lane = tid & 31;
    const int g = lane >> 2, tg = lane & 3;
    const int b = blockIdx.y, q0 = blockIdx.x * TILE;

    const __half* gq = g_q + (size_t)(b * NTOK + q0) * CCH;
    const __half* gk = g_k + (size_t)b * NTOK * CCH;
    const __half* gv = g_v + (size_t)b * NTOK * CCH;

    #pragma unroll
    for (int it = 0; it < 8; ++it) {
        int idx = it * 256 + tid;
        int row = idx >> 4, c = idx & 15;
        uint32_t so = (uint32_t)(row * 256 + swz(c, row) * 16);
        cp16(smb + OFF_Q + so, (const char*)gq + idx * 16);
        cp16(smb + OFF_K + so, (const char*)gk + idx * 16);
        cp16(smb + OFF_V + so, (const char*)gv + idx * 16);
    }
    cp_commit();
    cp_wait_all();
    __syncthreads();

    // Q fragments (persist)
    uint32_t qa[8][4];
    {
        int qrow = 16 * wid + (lane & 7) + 8 * ((lane >> 3) & 1);
        int coff = (lane >> 4) & 1;
        #pragma unroll
        for (int kc = 0; kc < 8; ++kc)
            ldm4(qa[kc], smb + OFF_Q +
                 (uint32_t)(qrow * 256 + swz(2 * kc + coff, qrow) * 16));
    }

    float oacc[16][4];
    #pragma unroll
    for (int j = 0; j < 16; ++j)
        #pragma unroll
        for (int e = 0; e < 4; ++e) oacc[j][e] = 0.f;
    float rs0 = 0.f, rs1 = 0.f;

    const int krl = (lane & 7) + 8 * ((lane >> 4) & 1);
    const int kco = (lane >> 3) & 1;
    const int vrl = (lane & 7) + 8 * ((lane >> 3) & 1);
    const int vco = (lane >> 4) & 1;

    for (int kt = 0; kt < NT; ++kt) {
        const uint32_t kb = smb + OFF_K + (uint32_t)(kt & 1) * 32768u;
        const uint32_t vb = smb + OFF_V + (uint32_t)(kt & 1) * 32768u;

        if (kt + 1 < NT) {
            const char* kk = (const char*)(gk + (size_t)(kt + 1) * TILE * CCH);
            const char* vv = (const char*)(gv + (size_t)(kt + 1) * TILE * CCH);
            uint32_t kb2 = smb + OFF_K + (uint32_t)((kt + 1) & 1) * 32768u;
            uint32_t vb2 = smb + OFF_V + (uint32_t)((kt + 1) & 1) * 32768u;
            #pragma unroll
            for (int it = 0; it < 8; ++it) {
                int idx = it * 256 + tid;
                int row = idx >> 4, c = idx & 15;
                uint32_t so = (uint32_t)(row * 256 + swz(c, row) * 16);
                cp16(kb2 + so, kk + idx * 16);
                cp16(vb2 + so, vv + idx * 16);
            }
            cp_commit();
        }

        // ---- S = Q K^T : kc outer / n2 inner (independent accumulators) ----
        float sacc[16][4];
        #pragma unroll
        for (int j = 0; j < 16; ++j)
            #pragma unroll
            for (int e = 0; e < 4; ++e) sacc[j][e] = 0.f;

        #pragma unroll
        for (int kc = 0; kc < 8; ++kc) {
            #pragma unroll
            for (int n2 = 0; n2 < 8; ++n2) {
                uint32_t kr[4];
                int key = 16 * n2 + krl;
                int c = 2 * kc + kco;
                ldm4(kr, kb + (uint32_t)(key * 256 + swz(c, key) * 16));
                mma_f32(sacc[2 * n2],     qa[kc], kr[0], kr[1]);
                mma_f32(sacc[2 * n2 + 1], qa[kc], kr[2], kr[3]);
            }
        }

        // ---- softmax (no max-sub) + PV per key-chunk ----
        #pragma unroll
        for (int kc = 0; kc < 8; ++kc) {
            float* s0 = sacc[2 * kc];
            float* s1 = sacc[2 * kc + 1];
            #pragma unroll
            for (int e = 0; e < 4; ++e) { s0[e] = __expf(s0[e]); s1[e] = __expf(s1[e]); }
            rs0 += s0[0] + s0[1] + s1[0] + s1[1];
            rs1 += s0[2] + s0[3] + s1[2] + s1[3];
            uint32_t pa[4] = { packh(s0[1], s0[0]), packh(s0[3], s0[2]),
                               packh(s1[1], s1[0]), packh(s1[3], s1[2]) };
            int key = 16 * kc + vrl;
            #pragma unroll
            for (int n2 = 0; n2 < 8; ++n2) {
                uint32_t vr[4];
                int c = 2 * n2 + vco;
                ldm4t(vr, vb + (uint32_t)(key * 256 + swz(c, key) * 16));
                mma_f32(oacc[2 * n2],     pa, vr[0], vr[1]);
                mma_f32(oacc[2 * n2 + 1], pa, vr[2], vr[3]);
            }
        }

        if (kt + 1 < NT) cp_wait_all();
        __syncthreads();
    }

    // ---- rowsum reduce across quad threads ----
    rs0 += __shfl_xor_sync(0xffffffffu, rs0, 1);
    rs0 += __shfl_xor_sync(0xffffffffu, rs0, 2);
    rs1 += __shfl_xor_sync(0xffffffffu, rs1, 1);
    rs1 += __shfl_xor_sync(0xffffffffu, rs1, 2);
    const float inv0 = 1.0f / rs0, inv1 = 1.0f / rs1;

    // ---- epilogue: out = x + acc / rowsum ----
    const int row0 = q0 + 16 * wid + g;
    const size_t base0 = ((size_t)b * NTOK + row0) * CCH;
    const size_t base1 = base0 + 8 * CCH;
    #pragma unroll
    for (int j = 0; j < 16; ++j) {
        int col = 8 * j + 2 * tg;
        float2 x0 = *(const float2*)(x + base0 + col);
        float2 x1 = *(const float2*)(x + base1 + col);
        float2 o0 = {x0.x + oacc[j][0] * inv0, x0.y + oacc[j][1] * inv0};
        float2 o1 = {x1.x + oacc[j][2] * inv1, x1.y + oacc[j][3] * inv1};
        *(float2*)(out + base0 + col) = o0;
        *(float2*)(out + base1 + col) = o1;
    }
}

// ---------------------------------------------------------------------------
extern "C" void kernel_launch(void* const* d_in, const int* in_sizes, int n_in,
                              void* d_out, int out_size)
{
    const float* x  = (const float*)d_in[0];
    const float* Wq = (const float*)d_in[1];
    const float* bq = (const float*)d_in[2];
    const float* Wk = (const float*)d_in[3];
    const float* bk = (const float*)d_in[4];
    const float* Wv = (const float*)d_in[5];
    const float* bv = (const float*)d_in[6];
    float* out = (float*)d_out;

    cudaFuncSetAttribute(qkv_mma,
                         cudaFuncAttributeMaxDynamicSharedMemorySize, QKV_SMEM);
    cudaFuncSetAttribute(attn_mma,
                         cudaFuncAttributeMaxDynamicSharedMemorySize, A_SMEM);

    qkv_mma<<<TOKENS_ALL / 128, 256, QKV_SMEM>>>(x, Wq, bq, Wk, bk, Wv, bv);
    attn_mma<<<dim3(NTOK / TILE, BTOT), 256, A_SMEM>>>(x, out);
}